// round 1
// baseline (speedup 1.0000x reference)
#include <cuda_runtime.h>
#include <math.h>

// Problem constants
#define Bn 4
#define Tn 2048
#define Dn 1024
#define Hn 16
#define HS 64
#define Mrows (Bn*Tn)          // 8192

// Scratch (device globals; no runtime allocation allowed)
__device__ float g_q[(size_t)Bn*Hn*Tn*HS];   // [B,H,T,hs] rope'd
__device__ float g_k[(size_t)Bn*Hn*Tn*HS];   // [B,H,T,hs] rope'd
__device__ float g_v[(size_t)Bn*Hn*Tn*HS];   // [B,H,T,hs]
__device__ float g_ao[(size_t)Bn*Tn*Dn];     // attention output [B*T, D]

// ---------------------------------------------------------------------------
// Generic SGEMM: C[M,N] = A[M,1024] @ W[N,1024]^T  (both row-major, K=1024)
// MODE 0: QKV epilogue — apply RoPE to k,q and scatter to g_k/g_q/g_v
// MODE 1: proj epilogue — add bias, write to out
// Tile 128x128xK16, 256 threads, 8x8 per-thread register blocking.
// ---------------------------------------------------------------------------
template<int MODE>
__global__ void __launch_bounds__(256) gemm128(const float* __restrict__ A,
                                               const float* __restrict__ W,
                                               const float* __restrict__ bias,
                                               float* __restrict__ out)
{
    __shared__ float As[16][132];
    __shared__ float Bs[16][132];

    const int m0 = blockIdx.y * 128;
    const int n0 = blockIdx.x * 128;
    const int tid = threadIdx.x;
    const int ty = tid >> 4;        // 0..15
    const int tx = tid & 15;        // 0..15
    const int lr = tid >> 2;        // 0..63
    const int lc = (tid & 3) << 2;  // 0,4,8,12

    const float* Abase = (MODE == 1) ? (const float*)g_ao : A;

    float acc[8][8];
    #pragma unroll
    for (int i = 0; i < 8; i++)
        #pragma unroll
        for (int j = 0; j < 8; j++) acc[i][j] = 0.f;

    const float* Ap0 = Abase + (size_t)(m0 + lr) * 1024 + lc;
    const float* Ap1 = Ap0 + (size_t)64 * 1024;
    const float* Wp0 = W + (size_t)(n0 + lr) * 1024 + lc;
    const float* Wp1 = Wp0 + (size_t)64 * 1024;

    for (int k0 = 0; k0 < 1024; k0 += 16) {
        float4 a0 = *(const float4*)(Ap0 + k0);
        float4 a1 = *(const float4*)(Ap1 + k0);
        float4 w0 = *(const float4*)(Wp0 + k0);
        float4 w1 = *(const float4*)(Wp1 + k0);
        __syncthreads();
        As[lc+0][lr] = a0.x; As[lc+1][lr] = a0.y; As[lc+2][lr] = a0.z; As[lc+3][lr] = a0.w;
        As[lc+0][lr+64] = a1.x; As[lc+1][lr+64] = a1.y; As[lc+2][lr+64] = a1.z; As[lc+3][lr+64] = a1.w;
        Bs[lc+0][lr] = w0.x; Bs[lc+1][lr] = w0.y; Bs[lc+2][lr] = w0.z; Bs[lc+3][lr] = w0.w;
        Bs[lc+0][lr+64] = w1.x; Bs[lc+1][lr+64] = w1.y; Bs[lc+2][lr+64] = w1.z; Bs[lc+3][lr+64] = w1.w;
        __syncthreads();
        #pragma unroll
        for (int kk = 0; kk < 16; kk++) {
            float a[8], b[8];
            *(float4*)&a[0] = *(const float4*)&As[kk][ty*8];
            *(float4*)&a[4] = *(const float4*)&As[kk][ty*8 + 4];
            *(float4*)&b[0] = *(const float4*)&Bs[kk][tx*8];
            *(float4*)&b[4] = *(const float4*)&Bs[kk][tx*8 + 4];
            #pragma unroll
            for (int i = 0; i < 8; i++)
                #pragma unroll
                for (int j = 0; j < 8; j++)
                    acc[i][j] = fmaf(a[i], b[j], acc[i][j]);
        }
    }

    if (MODE == 0) {
        // QKV + RoPE epilogue. cols: [0,1024)=k, [1024,2048)=q, [2048,3072)=v
        #pragma unroll
        for (int i = 0; i < 8; i++) {
            int m = m0 + ty*8 + i;
            int bb = m >> 11;        // /2048
            int t  = m & 2047;
            #pragma unroll
            for (int jp = 0; jp < 4; jp++) {
                int col = n0 + tx*8 + 2*jp;
                int which = col >> 10;
                int rem = col & 1023;
                int h = rem >> 6;
                int d = rem & 63;
                size_t off = ((size_t)((bb*Hn + h)*Tn + t))*HS + d;
                float e = acc[i][2*jp];
                float o = acc[i][2*jp + 1];
                if (which == 2) {
                    g_v[off] = e;
                    g_v[off + 1] = o;
                } else {
                    float ii = (float)(d >> 1);
                    float theta = powf(10000.0f, ii * (-2.0f / 64.0f));
                    float ang = (float)t * theta;
                    float sn, cs;
                    sincosf(ang, &sn, &cs);
                    float t1 = e*cs - o*sn;
                    float t2 = e*sn + o*cs;
                    float* g = (which == 0) ? g_k : g_q;
                    g[off] = t1;
                    g[off + 1] = t2;
                }
            }
        }
    } else {
        #pragma unroll
        for (int i = 0; i < 8; i++) {
            int m = m0 + ty*8 + i;
            #pragma unroll
            for (int j4 = 0; j4 < 2; j4++) {
                int col = n0 + tx*8 + j4*4;
                float4 r;
                r.x = acc[i][j4*4+0] + bias[col+0];
                r.y = acc[i][j4*4+1] + bias[col+1];
                r.z = acc[i][j4*4+2] + bias[col+2];
                r.w = acc[i][j4*4+3] + bias[col+3];
                *(float4*)(out + (size_t)m*1024 + col) = r;
            }
        }
    }
}

// ---------------------------------------------------------------------------
// Causal flash attention, fp32. One q-row per thread (128 rows / block).
// K/V tiles of 64 rows staged in smem; online softmax in 32-wide chunks.
// grid = (T/128, B*H)
// ---------------------------------------------------------------------------
__global__ void __launch_bounds__(128) attn_kernel()
{
    const int bh = blockIdx.y;   // b*16 + h
    const int qt = blockIdx.x;   // q tile index
    const int tid = threadIdx.x;
    const size_t base = (size_t)bh * Tn * HS;
    const float* Qp = g_q + base;
    const float* Kp = g_k + base;
    const float* Vp = g_v + base;
    const int r = qt*128 + tid;  // my q row (time index)

    __shared__ float Ks[64][68];
    __shared__ float Vs[64][68];

    float q[64], o[64];
    #pragma unroll
    for (int d4 = 0; d4 < 16; d4++) {
        float4 t4 = ((const float4*)(Qp + (size_t)r*HS))[d4];
        q[4*d4+0] = t4.x * 0.125f;
        q[4*d4+1] = t4.y * 0.125f;
        q[4*d4+2] = t4.z * 0.125f;
        q[4*d4+3] = t4.w * 0.125f;
    }
    #pragma unroll
    for (int d = 0; d < 64; d++) o[d] = 0.f;
    float mi = -INFINITY, li = 0.f;

    const int ntiles = 2*qt + 2;  // causal: only tiles with k <= max row of block
    for (int kt = 0; kt < ntiles; kt++) {
        __syncthreads();
        #pragma unroll
        for (int l = 0; l < 8; l++) {
            int idx = tid + l*128;          // 1024 float4 slots per tile
            int rr = idx >> 4;
            int cc = (idx & 15) << 2;
            *(float4*)&Ks[rr][cc] = *(const float4*)(Kp + ((size_t)(kt*64 + rr))*HS + cc);
            *(float4*)&Vs[rr][cc] = *(const float4*)(Vp + ((size_t)(kt*64 + rr))*HS + cc);
        }
        __syncthreads();

        #pragma unroll 1
        for (int ch = 0; ch < 2; ch++) {
            int jbase = kt*64 + ch*32;
            if (jbase > r) break;   // fully masked (and all later chunks too)
            float s[32];
            float cmax = -INFINITY;
            #pragma unroll
            for (int j = 0; j < 32; j++) {
                const float* kr = &Ks[ch*32 + j][0];
                float acc = 0.f;
                #pragma unroll
                for (int d4 = 0; d4 < 16; d4++) {
                    float4 kv = *(const float4*)(kr + 4*d4);
                    acc = fmaf(q[4*d4+0], kv.x, acc);
                    acc = fmaf(q[4*d4+1], kv.y, acc);
                    acc = fmaf(q[4*d4+2], kv.z, acc);
                    acc = fmaf(q[4*d4+3], kv.w, acc);
                }
                s[j] = (jbase + j <= r) ? acc : -INFINITY;
                cmax = fmaxf(cmax, s[j]);
            }
            float mnew = fmaxf(mi, cmax);
            float corr = __expf(mi - mnew);   // exp(-inf)=0 handles first chunk
            li *= corr;
            #pragma unroll
            for (int d = 0; d < 64; d++) o[d] *= corr;
            #pragma unroll
            for (int j = 0; j < 32; j++) {
                float p = __expf(s[j] - mnew);
                li += p;
                s[j] = p;
            }
            #pragma unroll
            for (int j = 0; j < 32; j++) {
                float p = s[j];
                const float* vr = &Vs[ch*32 + j][0];
                #pragma unroll
                for (int d4 = 0; d4 < 16; d4++) {
                    float4 vv = *(const float4*)(vr + 4*d4);
                    o[4*d4+0] = fmaf(p, vv.x, o[4*d4+0]);
                    o[4*d4+1] = fmaf(p, vv.y, o[4*d4+1]);
                    o[4*d4+2] = fmaf(p, vv.z, o[4*d4+2]);
                    o[4*d4+3] = fmaf(p, vv.w, o[4*d4+3]);
                }
            }
            mi = mnew;
        }
    }

    // normalize + write to [B*T, D] layout for the proj GEMM
    float inv = 1.f / li;
    int bb = bh >> 4;
    int h = bh & 15;
    size_t orow = ((size_t)(bb*Tn + r))*Dn + h*HS;
    #pragma unroll
    for (int d4 = 0; d4 < 16; d4++) {
        float4 w;
        w.x = o[4*d4+0]*inv;
        w.y = o[4*d4+1]*inv;
        w.z = o[4*d4+2]*inv;
        w.w = o[4*d4+3]*inv;
        *(float4*)(g_ao + orow + 4*d4) = w;
    }
}

// ---------------------------------------------------------------------------
extern "C" void kernel_launch(void* const* d_in, const int* in_sizes, int n_in,
                              void* d_out, int out_size)
{
    const float* x      = (const float*)d_in[0];  // [B,T,D]
    const float* w_kqv  = (const float*)d_in[1];  // [3D, D]
    const float* w_proj = (const float*)d_in[2];  // [D, D]
    const float* b_proj = (const float*)d_in[3];  // [D]
    float* out = (float*)d_out;                   // [B,T,D]

    dim3 g1(3*Dn/128, Mrows/128);   // 24 x 64
    gemm128<0><<<g1, 256>>>(x, w_kqv, nullptr, nullptr);

    dim3 g2(Tn/128, Bn*Hn);         // 16 x 64
    attn_kernel<<<g2, 128>>>();

    dim3 g3(Dn/128, Mrows/128);     // 8 x 64
    gemm128<1><<<g3, 256>>>(nullptr, w_proj, b_proj, out);
}

// round 2
// speedup vs baseline: 1.4115x; 1.4115x over previous
#include <cuda_runtime.h>
#include <math.h>
#include <stdint.h>

// Problem constants
#define Bn 4
#define Tn 2048
#define Dn 1024
#define Hn 16
#define HS 64
#define Mrows (Bn*Tn)          // 8192

// Scratch (device globals; no runtime allocation allowed)
__device__ float g_q[(size_t)Bn*Hn*Tn*HS];   // [B,H,T,hs] rope'd
__device__ float g_k[(size_t)Bn*Hn*Tn*HS];   // [B,H,T,hs] rope'd
__device__ float g_v[(size_t)Bn*Hn*Tn*HS];   // [B,H,T,hs]
__device__ float g_ao[(size_t)Bn*Tn*Dn];     // attention output [B*T, D]

// ---------------------------------------------------------------------------
// tf32 helpers
// ---------------------------------------------------------------------------
__device__ __forceinline__ uint32_t f2tf(float x) {
    uint32_t u;
    asm("cvt.rna.tf32.f32 %0, %1;" : "=r"(u) : "f"(x));
    return u;
}

__device__ __forceinline__ void mma_tf32(float c[4],
                                         uint32_t a0, uint32_t a1, uint32_t a2, uint32_t a3,
                                         uint32_t b0, uint32_t b1)
{
    asm volatile(
        "mma.sync.aligned.m16n8k8.row.col.f32.tf32.tf32.f32 "
        "{%0,%1,%2,%3}, {%4,%5,%6,%7}, {%8,%9}, {%0,%1,%2,%3};\n"
        : "+f"(c[0]), "+f"(c[1]), "+f"(c[2]), "+f"(c[3])
        : "r"(a0), "r"(a1), "r"(a2), "r"(a3), "r"(b0), "r"(b1));
}

// swizzled smem index for [row][k] tile, 16 k-entries per row, no padding
__device__ __forceinline__ int sw_idx(int row, int k) {
    return row * 16 + (k ^ (((row >> 1) & 3) << 2));
}

// ---------------------------------------------------------------------------
// tf32 tensor-core GEMM: C[M,N] = A[M,1024] @ W[N,1024]^T (row-major)
// Block 128x128, BK=16, 256 threads = 8 warps (2x4), warp tile 64x32.
// MODE 0: QKV epilogue (RoPE scatter to g_q/g_k/g_v)
// MODE 1: proj epilogue (bias add -> out), A taken from g_ao
// ---------------------------------------------------------------------------
template<int MODE>
__global__ void __launch_bounds__(256) gemm_tf32(const float* __restrict__ A,
                                                 const float* __restrict__ W,
                                                 const float* __restrict__ bias,
                                                 float* __restrict__ out)
{
    __shared__ __align__(16) uint32_t As[128 * 16];
    __shared__ __align__(16) uint32_t Ws[128 * 16];

    const int m0 = blockIdx.y * 128;
    const int n0 = blockIdx.x * 128;
    const int tid = threadIdx.x;
    const int wid = tid >> 5;
    const int lane = tid & 31;
    const int wm = wid >> 2;          // 0..1 -> 64 rows
    const int wn = wid & 3;           // 0..3 -> 32 cols
    const int gq = lane >> 2;         // 0..7
    const int tq = lane & 3;          // 0..3

    // global->smem mapping: row = tid>>2 (0..63, two chunks), kc = (tid&3)*4
    const int lrow = tid >> 2;
    const int lkc = (tid & 3) << 2;
    const int sw0 = sw_idx(lrow, lkc);
    const int sw1 = sw0 + 64 * 16;    // ((lrow+64)>>1)&3 == (lrow>>1)&3

    const float* Abase = (MODE == 1) ? (const float*)g_ao : A;
    const float* Ap0 = Abase + (size_t)(m0 + lrow) * 1024 + lkc;
    const float* Ap1 = Ap0 + (size_t)64 * 1024;
    const float* Wp0 = W + (size_t)(n0 + lrow) * 1024 + lkc;
    const float* Wp1 = Wp0 + (size_t)64 * 1024;

    float acc[4][4][4];
    #pragma unroll
    for (int mt = 0; mt < 4; mt++)
        #pragma unroll
        for (int nt = 0; nt < 4; nt++)
            #pragma unroll
            for (int r = 0; r < 4; r++) acc[mt][nt][r] = 0.f;

    float4 a0v = *(const float4*)(Ap0);
    float4 a1v = *(const float4*)(Ap1);
    float4 w0v = *(const float4*)(Wp0);
    float4 w1v = *(const float4*)(Wp1);

    for (int k0 = 0; k0 < 1024; k0 += 16) {
        __syncthreads();
        {
            uint4 u;
            u.x = f2tf(a0v.x); u.y = f2tf(a0v.y); u.z = f2tf(a0v.z); u.w = f2tf(a0v.w);
            *(uint4*)&As[sw0] = u;
            u.x = f2tf(a1v.x); u.y = f2tf(a1v.y); u.z = f2tf(a1v.z); u.w = f2tf(a1v.w);
            *(uint4*)&As[sw1] = u;
            u.x = f2tf(w0v.x); u.y = f2tf(w0v.y); u.z = f2tf(w0v.z); u.w = f2tf(w0v.w);
            *(uint4*)&Ws[sw0] = u;
            u.x = f2tf(w1v.x); u.y = f2tf(w1v.y); u.z = f2tf(w1v.z); u.w = f2tf(w1v.w);
            *(uint4*)&Ws[sw1] = u;
        }
        __syncthreads();

        if (k0 + 16 < 1024) {
            a0v = *(const float4*)(Ap0 + k0 + 16);
            a1v = *(const float4*)(Ap1 + k0 + 16);
            w0v = *(const float4*)(Wp0 + k0 + 16);
            w1v = *(const float4*)(Wp1 + k0 + 16);
        }

        #pragma unroll
        for (int ks = 0; ks < 2; ks++) {
            uint32_t af[4][4];
            uint32_t bf[4][2];
            #pragma unroll
            for (int mt = 0; mt < 4; mt++) {
                int mb = wm * 64 + mt * 16 + gq;
                int swm = ((mb >> 1) & 3) << 2;
                int klo = ks * 8 + tq;
                af[mt][0] = As[mb * 16 + (klo ^ swm)];
                af[mt][1] = As[(mb + 8) * 16 + (klo ^ swm)];
                af[mt][2] = As[mb * 16 + ((klo + 4) ^ swm)];
                af[mt][3] = As[(mb + 8) * 16 + ((klo + 4) ^ swm)];
            }
            #pragma unroll
            for (int nt = 0; nt < 4; nt++) {
                int nb = wn * 32 + nt * 8 + gq;
                int swn = ((nb >> 1) & 3) << 2;
                int klo = ks * 8 + tq;
                bf[nt][0] = Ws[nb * 16 + (klo ^ swn)];
                bf[nt][1] = Ws[nb * 16 + ((klo + 4) ^ swn)];
            }
            #pragma unroll
            for (int mt = 0; mt < 4; mt++)
                #pragma unroll
                for (int nt = 0; nt < 4; nt++)
                    mma_tf32(acc[mt][nt], af[mt][0], af[mt][1], af[mt][2], af[mt][3],
                             bf[nt][0], bf[nt][1]);
        }
    }

    // -------------------- epilogues --------------------
    if (MODE == 0) {
        // fragment c layout: c0=(row g, col 2t), c1=(g, 2t+1), c2=(g+8, 2t), c3=(g+8, 2t+1)
        #pragma unroll
        for (int mt = 0; mt < 4; mt++) {
            #pragma unroll
            for (int r = 0; r < 2; r++) {
                int m = m0 + wm * 64 + mt * 16 + gq + r * 8;
                int bb = m >> 11;
                int tt = m & 2047;
                #pragma unroll
                for (int nt = 0; nt < 4; nt++) {
                    int col = n0 + wn * 32 + nt * 8 + 2 * tq;
                    int which = col >> 10;
                    int rem = col & 1023;
                    int h = rem >> 6;
                    int d = rem & 63;
                    size_t off = ((size_t)((bb * Hn + h) * Tn + tt)) * HS + d;
                    float e = acc[mt][nt][r * 2 + 0];
                    float o = acc[mt][nt][r * 2 + 1];
                    if (which == 2) {
                        float2 v2 = make_float2(e, o);
                        *(float2*)(g_v + off) = v2;
                    } else {
                        float ii = (float)(d >> 1);
                        float theta = powf(10000.0f, ii * (-2.0f / 64.0f));
                        float ang = (float)tt * theta;
                        float sn, cs;
                        sincosf(ang, &sn, &cs);
                        float2 v2 = make_float2(e * cs - o * sn, e * sn + o * cs);
                        float* g = (which == 0) ? g_k : g_q;
                        *(float2*)(g + off) = v2;
                    }
                }
            }
        }
    } else {
        #pragma unroll
        for (int mt = 0; mt < 4; mt++) {
            #pragma unroll
            for (int r = 0; r < 2; r++) {
                int m = m0 + wm * 64 + mt * 16 + gq + r * 8;
                #pragma unroll
                for (int nt = 0; nt < 4; nt++) {
                    int col = n0 + wn * 32 + nt * 8 + 2 * tq;
                    float2 v2;
                    v2.x = acc[mt][nt][r * 2 + 0] + bias[col + 0];
                    v2.y = acc[mt][nt][r * 2 + 1] + bias[col + 1];
                    *(float2*)(out + (size_t)m * 1024 + col) = v2;
                }
            }
        }
    }
}

// ---------------------------------------------------------------------------
// Causal flash attention, fp32 (unchanged from round 1).
// ---------------------------------------------------------------------------
__global__ void __launch_bounds__(128) attn_kernel()
{
    const int bh = blockIdx.y;
    const int qt = blockIdx.x;
    const int tid = threadIdx.x;
    const size_t base = (size_t)bh * Tn * HS;
    const float* Qp = g_q + base;
    const float* Kp = g_k + base;
    const float* Vp = g_v + base;
    const int r = qt*128 + tid;

    __shared__ float Ks[64][68];
    __shared__ float Vs[64][68];

    float q[64], o[64];
    #pragma unroll
    for (int d4 = 0; d4 < 16; d4++) {
        float4 t4 = ((const float4*)(Qp + (size_t)r*HS))[d4];
        q[4*d4+0] = t4.x * 0.125f;
        q[4*d4+1] = t4.y * 0.125f;
        q[4*d4+2] = t4.z * 0.125f;
        q[4*d4+3] = t4.w * 0.125f;
    }
    #pragma unroll
    for (int d = 0; d < 64; d++) o[d] = 0.f;
    float mi = -INFINITY, li = 0.f;

    const int ntiles = 2*qt + 2;
    for (int kt = 0; kt < ntiles; kt++) {
        __syncthreads();
        #pragma unroll
        for (int l = 0; l < 8; l++) {
            int idx = tid + l*128;
            int rr = idx >> 4;
            int cc = (idx & 15) << 2;
            *(float4*)&Ks[rr][cc] = *(const float4*)(Kp + ((size_t)(kt*64 + rr))*HS + cc);
            *(float4*)&Vs[rr][cc] = *(const float4*)(Vp + ((size_t)(kt*64 + rr))*HS + cc);
        }
        __syncthreads();

        #pragma unroll 1
        for (int ch = 0; ch < 2; ch++) {
            int jbase = kt*64 + ch*32;
            if (jbase > r) break;
            float s[32];
            float cmax = -INFINITY;
            #pragma unroll
            for (int j = 0; j < 32; j++) {
                const float* kr = &Ks[ch*32 + j][0];
                float acc = 0.f;
                #pragma unroll
                for (int d4 = 0; d4 < 16; d4++) {
                    float4 kv = *(const float4*)(kr + 4*d4);
                    acc = fmaf(q[4*d4+0], kv.x, acc);
                    acc = fmaf(q[4*d4+1], kv.y, acc);
                    acc = fmaf(q[4*d4+2], kv.z, acc);
                    acc = fmaf(q[4*d4+3], kv.w, acc);
                }
                s[j] = (jbase + j <= r) ? acc : -INFINITY;
                cmax = fmaxf(cmax, s[j]);
            }
            float mnew = fmaxf(mi, cmax);
            float corr = __expf(mi - mnew);
            li *= corr;
            #pragma unroll
            for (int d = 0; d < 64; d++) o[d] *= corr;
            #pragma unroll
            for (int j = 0; j < 32; j++) {
                float p = __expf(s[j] - mnew);
                li += p;
                s[j] = p;
            }
            #pragma unroll
            for (int j = 0; j < 32; j++) {
                float p = s[j];
                const float* vr = &Vs[ch*32 + j][0];
                #pragma unroll
                for (int d4 = 0; d4 < 16; d4++) {
                    float4 vv = *(const float4*)(vr + 4*d4);
                    o[4*d4+0] = fmaf(p, vv.x, o[4*d4+0]);
                    o[4*d4+1] = fmaf(p, vv.y, o[4*d4+1]);
                    o[4*d4+2] = fmaf(p, vv.z, o[4*d4+2]);
                    o[4*d4+3] = fmaf(p, vv.w, o[4*d4+3]);
                }
            }
            mi = mnew;
        }
    }

    float inv = 1.f / li;
    int bb = bh >> 4;
    int h = bh & 15;
    size_t orow = ((size_t)(bb*Tn + r))*Dn + h*HS;
    #pragma unroll
    for (int d4 = 0; d4 < 16; d4++) {
        float4 w;
        w.x = o[4*d4+0]*inv;
        w.y = o[4*d4+1]*inv;
        w.z = o[4*d4+2]*inv;
        w.w = o[4*d4+3]*inv;
        *(float4*)(g_ao + orow + 4*d4) = w;
    }
}

// ---------------------------------------------------------------------------
extern "C" void kernel_launch(void* const* d_in, const int* in_sizes, int n_in,
                              void* d_out, int out_size)
{
    const float* x      = (const float*)d_in[0];
    const float* w_kqv  = (const float*)d_in[1];
    const float* w_proj = (const float*)d_in[2];
    const float* b_proj = (const float*)d_in[3];
    float* out = (float*)d_out;

    dim3 g1(3*Dn/128, Mrows/128);   // 24 x 64
    gemm_tf32<0><<<g1, 256>>>(x, w_kqv, nullptr, nullptr);

    dim3 g2(Tn/128, Bn*Hn);         // 16 x 64
    attn_kernel<<<g2, 128>>>();

    dim3 g3(Dn/128, Mrows/128);     // 8 x 64
    gemm_tf32<1><<<g3, 256>>>(nullptr, w_proj, b_proj, out);
}

// round 3
// speedup vs baseline: 3.4847x; 2.4688x over previous
#include <cuda_runtime.h>
#include <math.h>
#include <stdint.h>

// Problem constants
#define Bn 4
#define Tn 2048
#define Dn 1024
#define Hn 16
#define HS 64
#define Mrows (Bn*Tn)          // 8192

// Scratch (device globals; no runtime allocation allowed)
__device__ float g_q[(size_t)Bn*Hn*Tn*HS];   // [B,H,T,hs] rope'd (scaled for attn)
__device__ float g_k[(size_t)Bn*Hn*Tn*HS];   // [B,H,T,hs] rope'd
__device__ float g_v[(size_t)Bn*Hn*Tn*HS];   // [B,H,T,hs]
__device__ float g_ao[(size_t)Bn*Tn*Dn];     // attention output [B*T, D]

// ---------------------------------------------------------------------------
// tf32 helpers
// ---------------------------------------------------------------------------
__device__ __forceinline__ uint32_t f2tf(float x) {
    uint32_t u;
    asm("cvt.rna.tf32.f32 %0, %1;" : "=r"(u) : "f"(x));
    return u;
}

__device__ __forceinline__ float ex2(float x) {
    float y;
    asm("ex2.approx.f32 %0, %1;" : "=f"(y) : "f"(x));
    return y;
}

__device__ __forceinline__ void mma_tf32(float c[4],
                                         uint32_t a0, uint32_t a1, uint32_t a2, uint32_t a3,
                                         uint32_t b0, uint32_t b1)
{
    asm volatile(
        "mma.sync.aligned.m16n8k8.row.col.f32.tf32.tf32.f32 "
        "{%0,%1,%2,%3}, {%4,%5,%6,%7}, {%8,%9}, {%0,%1,%2,%3};\n"
        : "+f"(c[0]), "+f"(c[1]), "+f"(c[2]), "+f"(c[3])
        : "r"(a0), "r"(a1), "r"(a2), "r"(a3), "r"(b0), "r"(b1));
}

// swizzled smem index for [row][k] tile, 16 k-entries per row, no padding
__device__ __forceinline__ int sw_idx(int row, int k) {
    return row * 16 + (k ^ (((row >> 1) & 3) << 2));
}

// ---------------------------------------------------------------------------
// tf32 tensor-core GEMM: C[M,N] = A[M,1024] @ W[N,1024]^T (row-major)
// Block 128x128, BK=16, 256 threads = 8 warps (2x4), warp tile 64x32.
// MODE 0: QKV epilogue (RoPE scatter to g_q/g_k/g_v; q pre-scaled for attn)
// MODE 1: proj epilogue (bias add -> out), A taken from g_ao
// ---------------------------------------------------------------------------
template<int MODE>
__global__ void __launch_bounds__(256) gemm_tf32(const float* __restrict__ A,
                                                 const float* __restrict__ W,
                                                 const float* __restrict__ bias,
                                                 float* __restrict__ out)
{
    __shared__ __align__(16) uint32_t As[128 * 16];
    __shared__ __align__(16) uint32_t Ws[128 * 16];

    const int m0 = blockIdx.y * 128;
    const int n0 = blockIdx.x * 128;
    const int tid = threadIdx.x;
    const int wid = tid >> 5;
    const int lane = tid & 31;
    const int wm = wid >> 2;          // 0..1 -> 64 rows
    const int wn = wid & 3;           // 0..3 -> 32 cols
    const int gq = lane >> 2;         // 0..7
    const int tq = lane & 3;          // 0..3

    const int lrow = tid >> 2;
    const int lkc = (tid & 3) << 2;
    const int sw0 = sw_idx(lrow, lkc);
    const int sw1 = sw0 + 64 * 16;

    const float* Abase = (MODE == 1) ? (const float*)g_ao : A;
    const float* Ap0 = Abase + (size_t)(m0 + lrow) * 1024 + lkc;
    const float* Ap1 = Ap0 + (size_t)64 * 1024;
    const float* Wp0 = W + (size_t)(n0 + lrow) * 1024 + lkc;
    const float* Wp1 = Wp0 + (size_t)64 * 1024;

    float acc[4][4][4];
    #pragma unroll
    for (int mt = 0; mt < 4; mt++)
        #pragma unroll
        for (int nt = 0; nt < 4; nt++)
            #pragma unroll
            for (int r = 0; r < 4; r++) acc[mt][nt][r] = 0.f;

    float4 a0v = *(const float4*)(Ap0);
    float4 a1v = *(const float4*)(Ap1);
    float4 w0v = *(const float4*)(Wp0);
    float4 w1v = *(const float4*)(Wp1);

    for (int k0 = 0; k0 < 1024; k0 += 16) {
        __syncthreads();
        {
            uint4 u;
            u.x = f2tf(a0v.x); u.y = f2tf(a0v.y); u.z = f2tf(a0v.z); u.w = f2tf(a0v.w);
            *(uint4*)&As[sw0] = u;
            u.x = f2tf(a1v.x); u.y = f2tf(a1v.y); u.z = f2tf(a1v.z); u.w = f2tf(a1v.w);
            *(uint4*)&As[sw1] = u;
            u.x = f2tf(w0v.x); u.y = f2tf(w0v.y); u.z = f2tf(w0v.z); u.w = f2tf(w0v.w);
            *(uint4*)&Ws[sw0] = u;
            u.x = f2tf(w1v.x); u.y = f2tf(w1v.y); u.z = f2tf(w1v.z); u.w = f2tf(w1v.w);
            *(uint4*)&Ws[sw1] = u;
        }
        __syncthreads();

        if (k0 + 16 < 1024) {
            a0v = *(const float4*)(Ap0 + k0 + 16);
            a1v = *(const float4*)(Ap1 + k0 + 16);
            w0v = *(const float4*)(Wp0 + k0 + 16);
            w1v = *(const float4*)(Wp1 + k0 + 16);
        }

        #pragma unroll
        for (int ks = 0; ks < 2; ks++) {
            uint32_t af[4][4];
            uint32_t bf[4][2];
            #pragma unroll
            for (int mt = 0; mt < 4; mt++) {
                int mb = wm * 64 + mt * 16 + gq;
                int swm = ((mb >> 1) & 3) << 2;
                int klo = ks * 8 + tq;
                af[mt][0] = As[mb * 16 + (klo ^ swm)];
                af[mt][1] = As[(mb + 8) * 16 + (klo ^ swm)];
                af[mt][2] = As[mb * 16 + ((klo + 4) ^ swm)];
                af[mt][3] = As[(mb + 8) * 16 + ((klo + 4) ^ swm)];
            }
            #pragma unroll
            for (int nt = 0; nt < 4; nt++) {
                int nb = wn * 32 + nt * 8 + gq;
                int swn = ((nb >> 1) & 3) << 2;
                int klo = ks * 8 + tq;
                bf[nt][0] = Ws[nb * 16 + (klo ^ swn)];
                bf[nt][1] = Ws[nb * 16 + ((klo + 4) ^ swn)];
            }
            #pragma unroll
            for (int mt = 0; mt < 4; mt++)
                #pragma unroll
                for (int nt = 0; nt < 4; nt++)
                    mma_tf32(acc[mt][nt], af[mt][0], af[mt][1], af[mt][2], af[mt][3],
                             bf[nt][0], bf[nt][1]);
        }
    }

    if (MODE == 0) {
        // q gets pre-scaled by softmax scale * log2(e) for the attention kernel
        const float QSC = 0.125f * 1.4426950408889634f;
        #pragma unroll
        for (int mt = 0; mt < 4; mt++) {
            #pragma unroll
            for (int r = 0; r < 2; r++) {
                int m = m0 + wm * 64 + mt * 16 + gq + r * 8;
                int bb = m >> 11;
                int tt = m & 2047;
                #pragma unroll
                for (int nt = 0; nt < 4; nt++) {
                    int col = n0 + wn * 32 + nt * 8 + 2 * tq;
                    int which = col >> 10;
                    int rem = col & 1023;
                    int h = rem >> 6;
                    int d = rem & 63;
                    size_t off = ((size_t)((bb * Hn + h) * Tn + tt)) * HS + d;
                    float e = acc[mt][nt][r * 2 + 0];
                    float o = acc[mt][nt][r * 2 + 1];
                    if (which == 2) {
                        *(float2*)(g_v + off) = make_float2(e, o);
                    } else {
                        float ii = (float)(d >> 1);
                        float theta = powf(10000.0f, ii * (-2.0f / 64.0f));
                        float ang = (float)tt * theta;
                        float sn, cs;
                        sincosf(ang, &sn, &cs);
                        float t1 = e * cs - o * sn;
                        float t2 = e * sn + o * cs;
                        if (which == 0) {
                            *(float2*)(g_k + off) = make_float2(t1, t2);
                        } else {
                            *(float2*)(g_q + off) = make_float2(t1 * QSC, t2 * QSC);
                        }
                    }
                }
            }
        }
    } else {
        #pragma unroll
        for (int mt = 0; mt < 4; mt++) {
            #pragma unroll
            for (int r = 0; r < 2; r++) {
                int m = m0 + wm * 64 + mt * 16 + gq + r * 8;
                #pragma unroll
                for (int nt = 0; nt < 4; nt++) {
                    int col = n0 + wn * 32 + nt * 8 + 2 * tq;
                    float2 v2;
                    v2.x = acc[mt][nt][r * 2 + 0] + bias[col + 0];
                    v2.y = acc[mt][nt][r * 2 + 1] + bias[col + 1];
                    *(float2*)(out + (size_t)m * 1024 + col) = v2;
                }
            }
        }
    }
}

// ---------------------------------------------------------------------------
// Tensor-core causal flash attention (tf32 mma.sync).
// Block: 128 q-rows, 8 warps x m16. K-tiles of 64 keys. d = 64.
// Q pre-scaled by (1/8)*log2(e); softmax in exp2 domain.
// smem: Ks[64][68] (tf32 bits), Vs[64][68] (tf32 bits), Ps[128][68] (float;
//       doubles as Q staging before mainloop; warp-private rows afterwards).
// grid = (16, 64)
// ---------------------------------------------------------------------------
#define SMEM_ATTN ((64*68*2 + 128*68) * 4)

__global__ void __launch_bounds__(256) attn_mma()
{
    extern __shared__ __align__(16) char smraw[];
    uint32_t* Ks = (uint32_t*)smraw;        // [64*68] tf32 bits
    uint32_t* Vs = Ks + 64 * 68;            // [64*68] tf32 bits
    float*    Ps = (float*)(Vs + 64 * 68);  // [128*68]

    const int bh = blockIdx.y;
    const int qt = blockIdx.x;
    const int tid = threadIdx.x;
    const int wid = tid >> 5;
    const int lane = tid & 31;
    const int gq = lane >> 2;
    const int tq = lane & 3;
    const int qb = qt * 128;
    const int wrow = wid * 16;

    const size_t base = (size_t)bh * Tn * HS;
    const float* Qp = g_q + base;
    const float* Kp = g_k + base;
    const float* Vp = g_v + base;

    // stage Q tile (already scaled) into Ps
    #pragma unroll
    for (int l = 0; l < 8; l++) {
        int idx = tid + l * 256;
        int rr = idx >> 4;
        int cc = (idx & 15) << 2;
        float4 v = *(const float4*)(Qp + (size_t)(qb + rr) * HS + cc);
        *(float4*)&Ps[rr * 68 + cc] = v;
    }
    __syncthreads();

    const int r0off = (wrow + gq) * 68;
    const int r1off = (wrow + gq + 8) * 68;

    uint32_t qf[8][4];
    #pragma unroll
    for (int kk = 0; kk < 8; kk++) {
        qf[kk][0] = f2tf(Ps[r0off + kk * 8 + tq]);
        qf[kk][1] = f2tf(Ps[r1off + kk * 8 + tq]);
        qf[kk][2] = f2tf(Ps[r0off + kk * 8 + tq + 4]);
        qf[kk][3] = f2tf(Ps[r1off + kk * 8 + tq + 4]);
    }
    __syncwarp();

    float O[8][4];
    #pragma unroll
    for (int nt = 0; nt < 8; nt++)
        #pragma unroll
        for (int r = 0; r < 4; r++) O[nt][r] = 0.f;
    float m0 = -INFINITY, m1 = -INFINITY;
    float l0 = 0.f, l1 = 0.f;

    const int ntiles = 2 * qt + 2;
    for (int kt = 0; kt < ntiles; kt++) {
        const int k0 = kt * 64;
        __syncthreads();
        #pragma unroll
        for (int l = 0; l < 4; l++) {
            int idx = tid + l * 256;
            int rr = idx >> 4;
            int cc = (idx & 15) << 2;
            float4 kv = *(const float4*)(Kp + (size_t)(k0 + rr) * HS + cc);
            float4 vv = *(const float4*)(Vp + (size_t)(k0 + rr) * HS + cc);
            uint4 ku; ku.x = f2tf(kv.x); ku.y = f2tf(kv.y); ku.z = f2tf(kv.z); ku.w = f2tf(kv.w);
            uint4 vu; vu.x = f2tf(vv.x); vu.y = f2tf(vv.y); vu.z = f2tf(vv.z); vu.w = f2tf(vv.w);
            *(uint4*)&Ks[rr * 68 + cc] = ku;
            *(uint4*)&Vs[rr * 68 + cc] = vu;
        }
        __syncthreads();

        if (k0 > qb + wrow + 15) continue;   // tile fully masked for this warp

        // ---- scores S = Q K^T (in exp2 domain) ----
        float S[8][4];
        #pragma unroll
        for (int nt = 0; nt < 8; nt++)
            #pragma unroll
            for (int r = 0; r < 4; r++) S[nt][r] = 0.f;

        #pragma unroll
        for (int kk = 0; kk < 8; kk++) {
            #pragma unroll
            for (int nt = 0; nt < 8; nt++) {
                uint32_t b0 = Ks[(nt * 8 + gq) * 68 + kk * 8 + tq];
                uint32_t b1 = Ks[(nt * 8 + gq) * 68 + kk * 8 + tq + 4];
                mma_tf32(S[nt], qf[kk][0], qf[kk][1], qf[kk][2], qf[kk][3], b0, b1);
            }
        }

        // ---- causal mask (diagonal tiles only) ----
        if (k0 + 63 > qb + wrow) {
            int row0 = qb + wrow + gq;
            #pragma unroll
            for (int nt = 0; nt < 8; nt++) {
                int col = k0 + nt * 8 + 2 * tq;
                if (col     > row0)     S[nt][0] = -INFINITY;
                if (col + 1 > row0)     S[nt][1] = -INFINITY;
                if (col     > row0 + 8) S[nt][2] = -INFINITY;
                if (col + 1 > row0 + 8) S[nt][3] = -INFINITY;
            }
        }

        // ---- online softmax ----
        float cm0 = -INFINITY, cm1 = -INFINITY;
        #pragma unroll
        for (int nt = 0; nt < 8; nt++) {
            cm0 = fmaxf(cm0, fmaxf(S[nt][0], S[nt][1]));
            cm1 = fmaxf(cm1, fmaxf(S[nt][2], S[nt][3]));
        }
        cm0 = fmaxf(cm0, __shfl_xor_sync(0xffffffff, cm0, 1));
        cm0 = fmaxf(cm0, __shfl_xor_sync(0xffffffff, cm0, 2));
        cm1 = fmaxf(cm1, __shfl_xor_sync(0xffffffff, cm1, 1));
        cm1 = fmaxf(cm1, __shfl_xor_sync(0xffffffff, cm1, 2));

        float mn0 = fmaxf(m0, cm0);
        float mn1 = fmaxf(m1, cm1);
        float c0 = ex2(m0 - mn0);
        float c1 = ex2(m1 - mn1);
        l0 *= c0; l1 *= c1;
        #pragma unroll
        for (int nt = 0; nt < 8; nt++) {
            O[nt][0] *= c0; O[nt][1] *= c0;
            O[nt][2] *= c1; O[nt][3] *= c1;
        }
        m0 = mn0; m1 = mn1;

        __syncwarp();   // prior tile's Ps reads (PV) done before overwrite
        #pragma unroll
        for (int nt = 0; nt < 8; nt++) {
            float p0 = ex2(S[nt][0] - mn0);
            float p1 = ex2(S[nt][1] - mn0);
            float p2 = ex2(S[nt][2] - mn1);
            float p3 = ex2(S[nt][3] - mn1);
            l0 += p0 + p1;
            l1 += p2 + p3;
            float2 w0; w0.x = __uint_as_float(f2tf(p0)); w0.y = __uint_as_float(f2tf(p1));
            float2 w1; w1.x = __uint_as_float(f2tf(p2)); w1.y = __uint_as_float(f2tf(p3));
            *(float2*)&Ps[r0off + nt * 8 + 2 * tq] = w0;
            *(float2*)&Ps[r1off + nt * 8 + 2 * tq] = w1;
        }
        __syncwarp();   // Ps writes visible to whole warp

        // ---- O += P V ----
        #pragma unroll
        for (int kk = 0; kk < 8; kk++) {
            uint32_t a0 = __float_as_uint(Ps[r0off + kk * 8 + tq]);
            uint32_t a1 = __float_as_uint(Ps[r1off + kk * 8 + tq]);
            uint32_t a2 = __float_as_uint(Ps[r0off + kk * 8 + tq + 4]);
            uint32_t a3 = __float_as_uint(Ps[r1off + kk * 8 + tq + 4]);
            #pragma unroll
            for (int nt = 0; nt < 8; nt++) {
                uint32_t b0 = Vs[(kk * 8 + tq) * 68 + nt * 8 + gq];
                uint32_t b1 = Vs[(kk * 8 + tq + 4) * 68 + nt * 8 + gq];
                mma_tf32(O[nt], a0, a1, a2, a3, b0, b1);
            }
        }
    }

    // ---- finalize: reduce l across quad, normalize, write g_ao ----
    l0 += __shfl_xor_sync(0xffffffff, l0, 1);
    l0 += __shfl_xor_sync(0xffffffff, l0, 2);
    l1 += __shfl_xor_sync(0xffffffff, l1, 1);
    l1 += __shfl_xor_sync(0xffffffff, l1, 2);
    float inv0 = 1.f / l0;
    float inv1 = 1.f / l1;

    const int bb = bh >> 4;
    const int h = bh & 15;
    const int r0g = qb + wrow + gq;
    #pragma unroll
    for (int nt = 0; nt < 8; nt++) {
        int col = h * 64 + nt * 8 + 2 * tq;
        float2 w0; w0.x = O[nt][0] * inv0; w0.y = O[nt][1] * inv0;
        float2 w1; w1.x = O[nt][2] * inv1; w1.y = O[nt][3] * inv1;
        *(float2*)(g_ao + (size_t)(bb * Tn + r0g) * Dn + col) = w0;
        *(float2*)(g_ao + (size_t)(bb * Tn + r0g + 8) * Dn + col) = w1;
    }
}

// ---------------------------------------------------------------------------
extern "C" void kernel_launch(void* const* d_in, const int* in_sizes, int n_in,
                              void* d_out, int out_size)
{
    const float* x      = (const float*)d_in[0];
    const float* w_kqv  = (const float*)d_in[1];
    const float* w_proj = (const float*)d_in[2];
    const float* b_proj = (const float*)d_in[3];
    float* out = (float*)d_out;

    cudaFuncSetAttribute(attn_mma, cudaFuncAttributeMaxDynamicSharedMemorySize, SMEM_ATTN);

    dim3 g1(3*Dn/128, Mrows/128);   // 24 x 64
    gemm_tf32<0><<<g1, 256>>>(x, w_kqv, nullptr, nullptr);

    dim3 g2(Tn/128, Bn*Hn);         // 16 x 64
    attn_mma<<<g2, 256, SMEM_ATTN>>>();

    dim3 g3(Dn/128, Mrows/128);     // 8 x 64
    gemm_tf32<1><<<g3, 256>>>(nullptr, w_proj, b_proj, out);
}

// round 4
// speedup vs baseline: 3.8716x; 1.1110x over previous
#include <cuda_runtime.h>
#include <math.h>
#include <stdint.h>

// Problem constants
#define Bn 4
#define Tn 2048
#define Dn 1024
#define Hn 16
#define HS 64
#define Mrows (Bn*Tn)          // 8192

// Scratch (device globals; no runtime allocation allowed)
__device__ float g_q[(size_t)Bn*Hn*Tn*HS];   // [B,H,T,hs] rope'd, scaled, tf32-rounded
__device__ float g_k[(size_t)Bn*Hn*Tn*HS];   // [B,H,T,hs] rope'd, tf32-rounded
__device__ float g_v[(size_t)Bn*Hn*Tn*HS];   // [B,H,T,hs] tf32-rounded
__device__ float g_ao[(size_t)Bn*Tn*Dn];     // attention output [B*T, D]
__device__ float2 g_rope[Tn*32];             // (cos, sin) table

// ---------------------------------------------------------------------------
// helpers
// ---------------------------------------------------------------------------
__device__ __forceinline__ uint32_t f2tf(float x) {
    uint32_t u;
    asm("cvt.rna.tf32.f32 %0, %1;" : "=r"(u) : "f"(x));
    return u;
}

__device__ __forceinline__ float ex2(float x) {
    float y;
    asm("ex2.approx.f32 %0, %1;" : "=f"(y) : "f"(x));
    return y;
}

__device__ __forceinline__ void mma_tf32(float c[4],
                                         uint32_t a0, uint32_t a1, uint32_t a2, uint32_t a3,
                                         uint32_t b0, uint32_t b1)
{
    asm volatile(
        "mma.sync.aligned.m16n8k8.row.col.f32.tf32.tf32.f32 "
        "{%0,%1,%2,%3}, {%4,%5,%6,%7}, {%8,%9}, {%0,%1,%2,%3};\n"
        : "+f"(c[0]), "+f"(c[1]), "+f"(c[2]), "+f"(c[3])
        : "r"(a0), "r"(a1), "r"(a2), "r"(a3), "r"(b0), "r"(b1));
}

__device__ __forceinline__ int sw_idx(int row, int k) {
    return row * 16 + (k ^ (((row >> 1) & 3) << 2));
}

// ---------------------------------------------------------------------------
// RoPE table init (same powf/sincosf path that verified at 1.2e-6 in fp32)
// ---------------------------------------------------------------------------
__global__ void rope_init()
{
    int idx = blockIdx.x * blockDim.x + threadIdx.x;  // 0..65535
    int t = idx >> 5;
    int i = idx & 31;
    float theta = powf(10000.0f, (float)i * (-2.0f / 64.0f));
    float ang = (float)t * theta;
    float sn, cs;
    sincosf(ang, &sn, &cs);
    g_rope[idx] = make_float2(cs, sn);
}

// ---------------------------------------------------------------------------
// tf32 tensor-core GEMM: C[M,N] = A[M,1024] @ W[N,1024]^T (row-major)
// Block 128x128, BK=16, 256 threads = 8 warps (2x4), warp tile 64x32.
// MODE 0: QKV epilogue (table-RoPE scatter; outputs tf32-rounded)
// MODE 1: proj epilogue (bias add -> out), A taken from g_ao
// ---------------------------------------------------------------------------
template<int MODE>
__global__ void __launch_bounds__(256) gemm_tf32(const float* __restrict__ A,
                                                 const float* __restrict__ W,
                                                 const float* __restrict__ bias,
                                                 float* __restrict__ out)
{
    __shared__ __align__(16) uint32_t As[128 * 16];
    __shared__ __align__(16) uint32_t Ws[128 * 16];

    const int m0 = blockIdx.y * 128;
    const int n0 = blockIdx.x * 128;
    const int tid = threadIdx.x;
    const int wid = tid >> 5;
    const int lane = tid & 31;
    const int wm = wid >> 2;
    const int wn = wid & 3;
    const int gq = lane >> 2;
    const int tq = lane & 3;

    const int lrow = tid >> 2;
    const int lkc = (tid & 3) << 2;
    const int sw0 = sw_idx(lrow, lkc);
    const int sw1 = sw0 + 64 * 16;

    const float* Abase = (MODE == 1) ? (const float*)g_ao : A;
    const float* Ap0 = Abase + (size_t)(m0 + lrow) * 1024 + lkc;
    const float* Ap1 = Ap0 + (size_t)64 * 1024;
    const float* Wp0 = W + (size_t)(n0 + lrow) * 1024 + lkc;
    const float* Wp1 = Wp0 + (size_t)64 * 1024;

    float acc[4][4][4];
    #pragma unroll
    for (int mt = 0; mt < 4; mt++)
        #pragma unroll
        for (int nt = 0; nt < 4; nt++)
            #pragma unroll
            for (int r = 0; r < 4; r++) acc[mt][nt][r] = 0.f;

    float4 a0v = *(const float4*)(Ap0);
    float4 a1v = *(const float4*)(Ap1);
    float4 w0v = *(const float4*)(Wp0);
    float4 w1v = *(const float4*)(Wp1);

    for (int k0 = 0; k0 < 1024; k0 += 16) {
        __syncthreads();
        {
            uint4 u;
            u.x = f2tf(a0v.x); u.y = f2tf(a0v.y); u.z = f2tf(a0v.z); u.w = f2tf(a0v.w);
            *(uint4*)&As[sw0] = u;
            u.x = f2tf(a1v.x); u.y = f2tf(a1v.y); u.z = f2tf(a1v.z); u.w = f2tf(a1v.w);
            *(uint4*)&As[sw1] = u;
            u.x = f2tf(w0v.x); u.y = f2tf(w0v.y); u.z = f2tf(w0v.z); u.w = f2tf(w0v.w);
            *(uint4*)&Ws[sw0] = u;
            u.x = f2tf(w1v.x); u.y = f2tf(w1v.y); u.z = f2tf(w1v.z); u.w = f2tf(w1v.w);
            *(uint4*)&Ws[sw1] = u;
        }
        __syncthreads();

        if (k0 + 16 < 1024) {
            a0v = *(const float4*)(Ap0 + k0 + 16);
            a1v = *(const float4*)(Ap1 + k0 + 16);
            w0v = *(const float4*)(Wp0 + k0 + 16);
            w1v = *(const float4*)(Wp1 + k0 + 16);
        }

        #pragma unroll
        for (int ks = 0; ks < 2; ks++) {
            uint32_t af[4][4];
            uint32_t bf[4][2];
            #pragma unroll
            for (int mt = 0; mt < 4; mt++) {
                int mb = wm * 64 + mt * 16 + gq;
                int swm = ((mb >> 1) & 3) << 2;
                int klo = ks * 8 + tq;
                af[mt][0] = As[mb * 16 + (klo ^ swm)];
                af[mt][1] = As[(mb + 8) * 16 + (klo ^ swm)];
                af[mt][2] = As[mb * 16 + ((klo + 4) ^ swm)];
                af[mt][3] = As[(mb + 8) * 16 + ((klo + 4) ^ swm)];
            }
            #pragma unroll
            for (int nt = 0; nt < 4; nt++) {
                int nb = wn * 32 + nt * 8 + gq;
                int swn = ((nb >> 1) & 3) << 2;
                int klo = ks * 8 + tq;
                bf[nt][0] = Ws[nb * 16 + (klo ^ swn)];
                bf[nt][1] = Ws[nb * 16 + ((klo + 4) ^ swn)];
            }
            #pragma unroll
            for (int mt = 0; mt < 4; mt++)
                #pragma unroll
                for (int nt = 0; nt < 4; nt++)
                    mma_tf32(acc[mt][nt], af[mt][0], af[mt][1], af[mt][2], af[mt][3],
                             bf[nt][0], bf[nt][1]);
        }
    }

    if (MODE == 0) {
        const float QSC = 0.125f * 1.4426950408889634f;  // scale * log2(e)
        #pragma unroll
        for (int mt = 0; mt < 4; mt++) {
            #pragma unroll
            for (int r = 0; r < 2; r++) {
                int m = m0 + wm * 64 + mt * 16 + gq + r * 8;
                int bb = m >> 11;
                int tt = m & 2047;
                #pragma unroll
                for (int nt = 0; nt < 4; nt++) {
                    int col = n0 + wn * 32 + nt * 8 + 2 * tq;
                    int which = col >> 10;
                    int rem = col & 1023;
                    int h = rem >> 6;
                    int d = rem & 63;
                    size_t off = ((size_t)((bb * Hn + h) * Tn + tt)) * HS + d;
                    float e = acc[mt][nt][r * 2 + 0];
                    float o = acc[mt][nt][r * 2 + 1];
                    if (which == 2) {
                        float2 v2;
                        v2.x = __uint_as_float(f2tf(e));
                        v2.y = __uint_as_float(f2tf(o));
                        *(float2*)(g_v + off) = v2;
                    } else {
                        float2 cs = g_rope[tt * 32 + (d >> 1)];
                        float t1 = e * cs.x - o * cs.y;
                        float t2 = e * cs.y + o * cs.x;
                        float2 v2;
                        if (which == 0) {
                            v2.x = __uint_as_float(f2tf(t1));
                            v2.y = __uint_as_float(f2tf(t2));
                            *(float2*)(g_k + off) = v2;
                        } else {
                            v2.x = __uint_as_float(f2tf(t1 * QSC));
                            v2.y = __uint_as_float(f2tf(t2 * QSC));
                            *(float2*)(g_q + off) = v2;
                        }
                    }
                }
            }
        }
    } else {
        #pragma unroll
        for (int mt = 0; mt < 4; mt++) {
            #pragma unroll
            for (int r = 0; r < 2; r++) {
                int m = m0 + wm * 64 + mt * 16 + gq + r * 8;
                #pragma unroll
                for (int nt = 0; nt < 4; nt++) {
                    int col = n0 + wn * 32 + nt * 8 + 2 * tq;
                    float2 v2;
                    v2.x = acc[mt][nt][r * 2 + 0] + bias[col + 0];
                    v2.y = acc[mt][nt][r * 2 + 1] + bias[col + 1];
                    *(float2*)(out + (size_t)m * 1024 + col) = v2;
                }
            }
        }
    }
}

// ---------------------------------------------------------------------------
// Tensor-core causal flash attention (tf32 mma.sync), m32 warp tiles.
// Block: 128 q-rows, 4 warps x m32 (two m16 sub-tiles per warp).
// K/V fragments shared across sub-tiles -> ~1.25 LDS per MMA.
// K/V/Q already tf32-rounded in global; staging is a pure bit copy.
// grid = (16, 64), 128 threads, 2 blocks/SM.
// ---------------------------------------------------------------------------
#define SMEM_ATTN ((64*68*2 + 128*68) * 4)

__global__ void __launch_bounds__(128, 2) attn_mma()
{
    extern __shared__ __align__(16) char smraw[];
    uint32_t* Ks = (uint32_t*)smraw;        // [64*68] tf32 bits
    uint32_t* Vs = Ks + 64 * 68;            // [64*68] tf32 bits
    float*    Ps = (float*)(Vs + 64 * 68);  // [128*68] (Q staging, then P)

    const int bh = blockIdx.y;
    const int qt = blockIdx.x;
    const int tid = threadIdx.x;
    const int wid = tid >> 5;      // 0..3
    const int lane = tid & 31;
    const int gq = lane >> 2;
    const int tq = lane & 3;
    const int qb = qt * 128;
    const int wrow = wid * 32;

    const size_t base = (size_t)bh * Tn * HS;
    const float* Qp = g_q + base;
    const float* Kp = g_k + base;
    const float* Vp = g_v + base;

    // stage Q tile into Ps (128 rows x 64 cols, 128 threads -> 16 float4 each)
    #pragma unroll
    for (int l = 0; l < 16; l++) {
        int idx = tid + l * 128;
        int rr = idx >> 4;
        int cc = (idx & 15) << 2;
        float4 v = *(const float4*)(Qp + (size_t)(qb + rr) * HS + cc);
        *(float4*)&Ps[rr * 68 + cc] = v;
    }
    __syncthreads();

    // row offsets for the two m16 sub-tiles (warp-private rows of Ps)
    int roff[2][2];
    #pragma unroll
    for (int s = 0; s < 2; s++) {
        roff[s][0] = (wrow + 16 * s + gq) * 68;
        roff[s][1] = (wrow + 16 * s + gq + 8) * 68;
    }

    // Q fragments (already scaled + tf32-rounded)
    uint32_t qf[2][8][4];
    #pragma unroll
    for (int s = 0; s < 2; s++)
        #pragma unroll
        for (int kk = 0; kk < 8; kk++) {
            qf[s][kk][0] = __float_as_uint(Ps[roff[s][0] + kk * 8 + tq]);
            qf[s][kk][1] = __float_as_uint(Ps[roff[s][1] + kk * 8 + tq]);
            qf[s][kk][2] = __float_as_uint(Ps[roff[s][0] + kk * 8 + tq + 4]);
            qf[s][kk][3] = __float_as_uint(Ps[roff[s][1] + kk * 8 + tq + 4]);
        }
    // (Ps rows are warp-private; P overwrites only this warp's rows later)

    float O[2][8][4];
    #pragma unroll
    for (int s = 0; s < 2; s++)
        #pragma unroll
        for (int nt = 0; nt < 8; nt++)
            #pragma unroll
            for (int r = 0; r < 4; r++) O[s][nt][r] = 0.f;
    float mrow[2][2], lrow_[2][2];
    #pragma unroll
    for (int s = 0; s < 2; s++) {
        mrow[s][0] = -INFINITY; mrow[s][1] = -INFINITY;
        lrow_[s][0] = 0.f;      lrow_[s][1] = 0.f;
    }

    const int ntiles = 2 * qt + 2;
    for (int kt = 0; kt < ntiles; kt++) {
        const int k0 = kt * 64;
        __syncthreads();
        // stage K,V (bit copy; 64 rows x 16 float4 slots = 1024 slots / 128 thr)
        #pragma unroll
        for (int l = 0; l < 8; l++) {
            int idx = tid + l * 128;
            int rr = idx >> 4;
            int cc = (idx & 15) << 2;
            uint4 ku = *(const uint4*)(Kp + (size_t)(k0 + rr) * HS + cc);
            uint4 vu = *(const uint4*)(Vp + (size_t)(k0 + rr) * HS + cc);
            *(uint4*)&Ks[rr * 68 + cc] = ku;
            *(uint4*)&Vs[rr * 68 + cc] = vu;
        }
        __syncthreads();

        if (k0 > qb + wrow + 31) continue;   // fully masked for this warp

        // ---- S = Q K^T ----
        float S[2][8][4];
        #pragma unroll
        for (int s = 0; s < 2; s++)
            #pragma unroll
            for (int nt = 0; nt < 8; nt++)
                #pragma unroll
                for (int r = 0; r < 4; r++) S[s][nt][r] = 0.f;

        #pragma unroll
        for (int kk = 0; kk < 8; kk++) {
            #pragma unroll
            for (int nt = 0; nt < 8; nt++) {
                uint32_t b0 = Ks[(nt * 8 + gq) * 68 + kk * 8 + tq];
                uint32_t b1 = Ks[(nt * 8 + gq) * 68 + kk * 8 + tq + 4];
                mma_tf32(S[0][nt], qf[0][kk][0], qf[0][kk][1], qf[0][kk][2], qf[0][kk][3], b0, b1);
                mma_tf32(S[1][nt], qf[1][kk][0], qf[1][kk][1], qf[1][kk][2], qf[1][kk][3], b0, b1);
            }
        }

        // ---- causal mask (diagonal region only) ----
        if (k0 + 63 > qb + wrow) {
            #pragma unroll
            for (int s = 0; s < 2; s++) {
                int row0 = qb + wrow + 16 * s + gq;
                #pragma unroll
                for (int nt = 0; nt < 8; nt++) {
                    int col = k0 + nt * 8 + 2 * tq;
                    if (col     > row0)     S[s][nt][0] = -INFINITY;
                    if (col + 1 > row0)     S[s][nt][1] = -INFINITY;
                    if (col     > row0 + 8) S[s][nt][2] = -INFINITY;
                    if (col + 1 > row0 + 8) S[s][nt][3] = -INFINITY;
                }
            }
        }

        // ---- online softmax + P store ----
        __syncwarp();   // prior PV reads of Ps complete before overwrite
        #pragma unroll
        for (int s = 0; s < 2; s++) {
            float cm0 = -INFINITY, cm1 = -INFINITY;
            #pragma unroll
            for (int nt = 0; nt < 8; nt++) {
                cm0 = fmaxf(cm0, fmaxf(S[s][nt][0], S[s][nt][1]));
                cm1 = fmaxf(cm1, fmaxf(S[s][nt][2], S[s][nt][3]));
            }
            cm0 = fmaxf(cm0, __shfl_xor_sync(0xffffffff, cm0, 1));
            cm0 = fmaxf(cm0, __shfl_xor_sync(0xffffffff, cm0, 2));
            cm1 = fmaxf(cm1, __shfl_xor_sync(0xffffffff, cm1, 1));
            cm1 = fmaxf(cm1, __shfl_xor_sync(0xffffffff, cm1, 2));

            float mn0 = fmaxf(mrow[s][0], cm0);
            float mn1 = fmaxf(mrow[s][1], cm1);
            float c0 = ex2(mrow[s][0] - mn0);
            float c1 = ex2(mrow[s][1] - mn1);
            lrow_[s][0] *= c0; lrow_[s][1] *= c1;
            #pragma unroll
            for (int nt = 0; nt < 8; nt++) {
                O[s][nt][0] *= c0; O[s][nt][1] *= c0;
                O[s][nt][2] *= c1; O[s][nt][3] *= c1;
            }
            mrow[s][0] = mn0; mrow[s][1] = mn1;

            #pragma unroll
            for (int nt = 0; nt < 8; nt++) {
                float p0 = ex2(S[s][nt][0] - mn0);
                float p1 = ex2(S[s][nt][1] - mn0);
                float p2 = ex2(S[s][nt][2] - mn1);
                float p3 = ex2(S[s][nt][3] - mn1);
                lrow_[s][0] += p0 + p1;
                lrow_[s][1] += p2 + p3;
                float2 w0; w0.x = __uint_as_float(f2tf(p0)); w0.y = __uint_as_float(f2tf(p1));
                float2 w1; w1.x = __uint_as_float(f2tf(p2)); w1.y = __uint_as_float(f2tf(p3));
                *(float2*)&Ps[roff[s][0] + nt * 8 + 2 * tq] = w0;
                *(float2*)&Ps[roff[s][1] + nt * 8 + 2 * tq] = w1;
            }
        }
        __syncwarp();   // P visible to whole warp

        // ---- O += P V ----
        #pragma unroll
        for (int kk = 0; kk < 8; kk++) {
            uint32_t a[2][4];
            #pragma unroll
            for (int s = 0; s < 2; s++) {
                a[s][0] = __float_as_uint(Ps[roff[s][0] + kk * 8 + tq]);
                a[s][1] = __float_as_uint(Ps[roff[s][1] + kk * 8 + tq]);
                a[s][2] = __float_as_uint(Ps[roff[s][0] + kk * 8 + tq + 4]);
                a[s][3] = __float_as_uint(Ps[roff[s][1] + kk * 8 + tq + 4]);
            }
            #pragma unroll
            for (int nt = 0; nt < 8; nt++) {
                uint32_t b0 = Vs[(kk * 8 + tq) * 68 + nt * 8 + gq];
                uint32_t b1 = Vs[(kk * 8 + tq + 4) * 68 + nt * 8 + gq];
                mma_tf32(O[0][nt], a[0][0], a[0][1], a[0][2], a[0][3], b0, b1);
                mma_tf32(O[1][nt], a[1][0], a[1][1], a[1][2], a[1][3], b0, b1);
            }
        }
    }

    // ---- finalize ----
    const int bb = bh >> 4;
    const int h = bh & 15;
    #pragma unroll
    for (int s = 0; s < 2; s++) {
        float l0 = lrow_[s][0], l1 = lrow_[s][1];
        l0 += __shfl_xor_sync(0xffffffff, l0, 1);
        l0 += __shfl_xor_sync(0xffffffff, l0, 2);
        l1 += __shfl_xor_sync(0xffffffff, l1, 1);
        l1 += __shfl_xor_sync(0xffffffff, l1, 2);
        float inv0 = 1.f / l0;
        float inv1 = 1.f / l1;
        int r0g = qb + wrow + 16 * s + gq;
        #pragma unroll
        for (int nt = 0; nt < 8; nt++) {
            int col = h * 64 + nt * 8 + 2 * tq;
            float2 w0; w0.x = O[s][nt][0] * inv0; w0.y = O[s][nt][1] * inv0;
            float2 w1; w1.x = O[s][nt][2] * inv1; w1.y = O[s][nt][3] * inv1;
            *(float2*)(g_ao + (size_t)(bb * Tn + r0g) * Dn + col) = w0;
            *(float2*)(g_ao + (size_t)(bb * Tn + r0g + 8) * Dn + col) = w1;
        }
    }
}

// ---------------------------------------------------------------------------
extern "C" void kernel_launch(void* const* d_in, const int* in_sizes, int n_in,
                              void* d_out, int out_size)
{
    const float* x      = (const float*)d_in[0];
    const float* w_kqv  = (const float*)d_in[1];
    const float* w_proj = (const float*)d_in[2];
    const float* b_proj = (const float*)d_in[3];
    float* out = (float*)d_out;

    cudaFuncSetAttribute(attn_mma, cudaFuncAttributeMaxDynamicSharedMemorySize, SMEM_ATTN);

    rope_init<<<64, 1024>>>();

    dim3 g1(3*Dn/128, Mrows/128);   // 24 x 64
    gemm_tf32<0><<<g1, 256>>>(x, w_kqv, nullptr, nullptr);

    dim3 g2(Tn/128, Bn*Hn);         // 16 x 64
    attn_mma<<<g2, 128, SMEM_ATTN>>>();

    dim3 g3(Dn/128, Mrows/128);     // 8 x 64
    gemm_tf32<1><<<g3, 256>>>(nullptr, w_proj, b_proj, out);
}